// round 15
// baseline (speedup 1.0000x reference)
#include <cuda_runtime.h>
#include <cuda_fp16.h>
#include <math.h>

#define N_NODES 20000
#define NPAD    20032   // padded to multiple of 64 (proj tile)
#define N_EDGES 320000
#define E_TOT   340000  // edges + self loops
#define NFEAT   128
#define NHID    64
#define HEADS   4
#define HH      256     // HEADS*NHID
#define NCLASS  16

// softplus(1.0)
#define SP1 1.3132616875182228f

// ---------------- scratch (device globals, no allocation) ----------------
__device__ int    g_is64;
__device__ int    g_deg[N_NODES];   // ZERO invariant: statically zero; k_scan re-zeroes after reading
__device__ int    g_rowptr[N_NODES + 1];
__device__ int    g_cursor[N_NODES];
__device__ int    g_csrc[E_TOT];            // CSR-by-destination source list
__device__ float  g_watt[NHID*8];           // folded attention weights (4 src, 4 dst cols)
__device__ __align__(16) float  g_X[N_NODES*NHID];
__device__ __align__(16) float  g_Y[N_NODES*NHID];
__device__ __align__(16) __half g_Xh[NPAD*NHID];    // fp16 copy of X (proj input)
__device__ __align__(16) __half g_WgT[HH*NHID];     // fp16 Wg transposed [n][k]
__device__ __align__(16) __half g_h[NPAD*HH];       // fp16 projected features
__device__ __align__(16) float  g_asrc[NPAD*HEADS];
__device__ __align__(16) float  g_adst[NPAD*HEADS];

// decode one edge's (src,dst) from raw edge_index (int32 or int64)
__device__ __forceinline__ void edge_sd(const int* __restrict__ w, int e, int& s, int& d){
    if (e < N_EDGES){
        if (g_is64){ s = w[2*e]; d = w[2*(N_EDGES + e)]; }
        else       { s = w[e];   d = w[N_EDGES + e]; }
    } else {
        s = d = e - N_EDGES;                // self loop
    }
}

// ---------------- dtype detect (1 warp) ----------------
__global__ void k_detect(const unsigned* __restrict__ w){
    if (threadIdx.x == 0){
        // int64 inputs (< 2^31) have all-odd-word zeros in the first 128 words
        int all0 = 1;
        for (int i = 1; i < 128; i += 2) if (w[i] != 0u) all0 = 0;
        g_is64 = all0;
    }
}

// histogram: dst-only loads (src not needed here)
__global__ void k_hist(const int* __restrict__ w){
    int e = blockIdx.x * blockDim.x + threadIdx.x;
    if (e >= E_TOT) return;
    int d;
    if (e < N_EDGES) d = g_is64 ? w[2*(N_EDGES + e)] : w[N_EDGES + e];
    else             d = e - N_EDGES;       // self loop
    atomicAdd(&g_deg[d], 1);
}

// single-block, single-pass blocked exclusive scan: thread t owns 20 elements
// RE-ZEROES g_deg after reading (self-restoring invariant across graph replays)
#define SCAN_CH 20
__global__ void k_scan(){
    int t = threadIdx.x, lane = t & 31, w = t >> 5;
    int base = t * SCAN_CH;
    int v[SCAN_CH];
    int sum = 0;
#pragma unroll
    for (int i = 0; i < SCAN_CH; i++){
        int idx = base + i;
        if (idx < N_NODES){ v[i] = g_deg[idx]; g_deg[idx] = 0; }
        else v[i] = 0;
        sum += v[i];
    }
    int s = sum;
#pragma unroll
    for (int off = 1; off < 32; off <<= 1){
        int n = __shfl_up_sync(0xffffffffu, s, off);
        if (lane >= off) s += n;
    }
    __shared__ int wtot[32];
    if (lane == 31) wtot[w] = s;
    __syncthreads();
    if (w == 0){
        int ws = wtot[lane];
#pragma unroll
        for (int off = 1; off < 32; off <<= 1){
            int n = __shfl_up_sync(0xffffffffu, ws, off);
            if (lane >= off) ws += n;
        }
        wtot[lane] = ws;
    }
    __syncthreads();
    int excl = (s - sum) + (w > 0 ? wtot[w - 1] : 0);
    int run = excl;
#pragma unroll
    for (int i = 0; i < SCAN_CH; i++){
        int idx = base + i;
        if (idx < N_NODES){ g_rowptr[idx] = run; g_cursor[idx] = run; }
        run += v[i];
    }
    if (t == 1023) g_rowptr[N_NODES] = run;
}

__global__ void k_scatter(const int* __restrict__ w){
    int e = blockIdx.x * blockDim.x + threadIdx.x;
    if (e >= E_TOT) return;
    int s, d; edge_sd(w, e, s, d);
    int pos = atomicAdd(&g_cursor[d], 1);
    g_csrc[pos] = s;
}

// ---------------- encoder: Y = relu(x @ W_enc + b_enc); X = Y (fp32 + fp16 copy) ----------------
// extra last block: fold attention weights + transpose Wg to fp16
__global__ void k_encoder(const float* __restrict__ x,
                          const float* __restrict__ We,
                          const float* __restrict__ be,
                          const float* __restrict__ Wg,
                          const float* __restrict__ atts,
                          const float* __restrict__ attd){
    int t = threadIdx.x;
    if (blockIdx.x == N_NODES/16){
        // w_att = Wg @ [atts|attd]; thread t = row k of Wg, 8 outputs
#pragma unroll
        for (int o = 0; o < 8; o++){
            const float* av = (o < 4) ? (atts + (o & 3) * NHID) : (attd + (o & 3) * NHID);
            const float* wr = Wg + t * HH + (o & 3) * NHID;
            float a = 0.f;
#pragma unroll 8
            for (int f = 0; f < NHID; f++) a = fmaf(wr[f], av[f], a);
            g_watt[t * 8 + o] = a;
        }
        // WgT fp16 [n][k]
        for (int i = t; i < HH * NHID; i += 64){
            int n = i >> 6, k = i & 63;
            g_WgT[i] = __float2half_rn(Wg[k * HH + n]);
        }
        return;
    }
    int nb = blockIdx.x * 16;
    __shared__ float4 xs4[16][NFEAT/4];
    for (int r = t; r < 16 * (NFEAT/4); r += 64)
        xs4[r >> 5][r & 31] = ((const float4*)x)[(nb + (r >> 5)) * (NFEAT/4) + (r & 31)];
    __syncthreads();
    float acc[16];
    float b = be[t];
#pragma unroll
    for (int m = 0; m < 16; m++) acc[m] = b;
    for (int k4 = 0; k4 < NFEAT/4; k4++){
        float w0 = We[(4*k4+0) * NHID + t];
        float w1 = We[(4*k4+1) * NHID + t];
        float w2 = We[(4*k4+2) * NHID + t];
        float w3 = We[(4*k4+3) * NHID + t];
#pragma unroll
        for (int m = 0; m < 16; m++){
            float4 xv = xs4[m][k4];
            acc[m] = fmaf(xv.x, w0, acc[m]);
            acc[m] = fmaf(xv.y, w1, acc[m]);
            acc[m] = fmaf(xv.z, w2, acc[m]);
            acc[m] = fmaf(xv.w, w3, acc[m]);
        }
    }
#pragma unroll
    for (int m = 0; m < 16; m++){
        float v = fmaxf(acc[m], 0.f);
        g_Y[(nb + m) * NHID + t] = v;
        g_X[(nb + m) * NHID + t] = v;
        g_Xh[(nb + m) * NHID + t] = __float2half_rn(v);
    }
}

// ---------------- per-layer projection via HMMA: h = X @ W_gat (+ a_src/a_dst) ----------------
// 64 nodes per block, 256 threads = 8 warps
// warp w: m-group = w&3 (rows (w&3)*16..+15), n-half = w>>2 (128 cols), 16 m16n8 tiles
// smem rows padded to 72 halves -> conflict-free fragment loads
__global__ void k_gat_proj(){
    __shared__ __half Xs[64*72];     // 9 KB
    __shared__ __half Ws[256*72];    // 36 KB
    __shared__ float  watt_s[NHID*8];// 2 KB
    int nb = blockIdx.x * 64;
    int t  = threadIdx.x;

#pragma unroll
    for (int i = 0; i < 2; i++){
        int idx = t + i*256;                 // 0..511 uint4s of X tile
        int row = idx >> 3, seg = idx & 7;
        uint4 v = ((const uint4*)g_Xh)[(nb + row)*8 + seg];
        *((uint4*)(Xs + row*72 + seg*8)) = v;
    }
#pragma unroll
    for (int i = 0; i < 8; i++){
        int idx = t + i*256;                 // 0..2047 uint4s of WgT
        int row = idx >> 3, seg = idx & 7;
        uint4 v = ((const uint4*)g_WgT)[idx];
        *((uint4*)(Ws + row*72 + seg*8)) = v;
    }
    for (int r = t; r < NHID*8; r += 256) watt_s[r] = g_watt[r];
    __syncthreads();

    int w = t >> 5, lane = t & 31;
    int gid = lane >> 2, tig = lane & 3;
    int mg = w & 3, nh = w >> 2;

    float acc[16][4];
#pragma unroll
    for (int i = 0; i < 16; i++){
        acc[i][0] = 0.f; acc[i][1] = 0.f; acc[i][2] = 0.f; acc[i][3] = 0.f;
    }
    const unsigned* Xs32 = (const unsigned*)Xs;   // b32 units, row stride 36
    const unsigned* Ws32 = (const unsigned*)Ws;
    int r0 = mg*16 + gid;
#pragma unroll
    for (int ks = 0; ks < 4; ks++){
        unsigned a0 = Xs32[ r0      *36 + ks*8     + tig];
        unsigned a1 = Xs32[(r0 + 8) *36 + ks*8     + tig];
        unsigned a2 = Xs32[ r0      *36 + ks*8 + 4 + tig];
        unsigned a3 = Xs32[(r0 + 8) *36 + ks*8 + 4 + tig];
#pragma unroll
        for (int nt = 0; nt < 16; nt++){
            int n = (nh*16 + nt)*8 + gid;
            unsigned b0 = Ws32[n*36 + ks*8     + tig];
            unsigned b1 = Ws32[n*36 + ks*8 + 4 + tig];
            asm volatile(
                "mma.sync.aligned.m16n8k16.row.col.f32.f16.f16.f32 "
                "{%0,%1,%2,%3}, {%4,%5,%6,%7}, {%8,%9}, {%0,%1,%2,%3};"
                : "+f"(acc[nt][0]), "+f"(acc[nt][1]), "+f"(acc[nt][2]), "+f"(acc[nt][3])
                : "r"(a0), "r"(a1), "r"(a2), "r"(a3), "r"(b0), "r"(b1));
        }
    }
    // epilogue: c0,c1 -> (row gid, cols 2tig,2tig+1); c2,c3 -> row gid+8
#pragma unroll
    for (int nt = 0; nt < 16; nt++){
        int c  = (nh*16 + nt)*8 + tig*2;
        int rr0 = nb + mg*16 + gid;
        ((half2*)g_h)[( rr0      * HH + c) >> 1] = __floats2half2_rn(acc[nt][0], acc[nt][1]);
        ((half2*)g_h)[((rr0 + 8) * HH + c) >> 1] = __floats2half2_rn(acc[nt][2], acc[nt][3]);
    }

    // attention scores from fp16 X: 512 outputs, 2 per thread
#pragma unroll
    for (int i = 0; i < 2; i++){
        int idx = t + i*256;
        int m = idx >> 3, o = idx & 7;
        float a = 0.f;
#pragma unroll 8
        for (int k = 0; k < NHID; k++)
            a = fmaf(__half2float(Xs[m*72 + k]), watt_s[k*8 + o], a);
        if (o < 4) g_asrc[(nb + m) * HEADS + o] = a;
        else       g_adst[(nb + m) * HEADS + (o - 4)] = a;
    }
}

// ---------------- fused per-node: attention + gather + normalize + GraphCON ----------------
// one block = one WARP = one destination node; lane t owns channels 8t..8t+7
// windows padded (clamped src, zero weight) so inner loop is branch-free unroll-4
// softmax without max-subtraction: ratios identical, |e| is small so exp is safe
// FINAL: skip dead g_Y / g_Xh stores in the last layer (g_X still feeds decoder)
template<bool FINAL>
__global__ void k_node_agg_t(const float* __restrict__ bg){
    int n = blockIdx.x;
    int t = threadIdx.x;                 // 0..31
    int hh = t >> 3;                     // head of this lane's channels
    int r0 = g_rowptr[n], deg = g_rowptr[n+1] - r0;

    __shared__ int   s_src[32];
    __shared__ float s_ex[HEADS][32];

    // prefetch epilogue operands (hide behind gather)
    float2 xv = ((const float2*)g_X)[n * 32 + t];
    float2 yv = ((const float2*)g_Y)[n * 32 + t];
    float4 bg0 = ((const float4*)bg)[2*t];
    float4 bg1 = ((const float4*)bg)[2*t + 1];
    float4 bdst = ((const float4*)g_adst)[n];

    const uint4* gh = (const uint4*)g_h;   // 8 halves per uint4; row stride HH/8 = 32
    float acc[8];
#pragma unroll
    for (int i = 0; i < 8; i++) acc[i] = 0.f;
    float dpart = 0.f;

    for (int base = 0; base < deg; base += 32){
        int cnt = min(32, deg - base);
        // stage all 32 lanes: clamp index, zero weight beyond cnt
        {
            int idx = base + t;
            int cl  = (idx < deg) ? idx : (deg - 1);
            float mask = (idx < deg) ? 1.f : 0.f;
            int s = g_csrc[r0 + cl];
            s_src[t] = s;
            float4 a = ((const float4*)g_asrc)[s];
            float v;
            v = a.x + bdst.x; v = (v > 0.f) ? v : 0.2f * v; s_ex[0][t] = __expf(v) * mask;
            v = a.y + bdst.y; v = (v > 0.f) ? v : 0.2f * v; s_ex[1][t] = __expf(v) * mask;
            v = a.z + bdst.z; v = (v > 0.f) ? v : 0.2f * v; s_ex[2][t] = __expf(v) * mask;
            v = a.w + bdst.w; v = (v > 0.f) ? v : 0.2f * v; s_ex[3][t] = __expf(v) * mask;
        }
        __syncwarp();
#pragma unroll
        for (int j = 0; j < 4; j++) dpart += s_ex[hh][(t & 7) + 8*j];
        int cntP = (cnt + 3) & ~3;
        for (int j = 0; j < cntP; j += 4){
            int s0 = s_src[j],   s1 = s_src[j+1];
            int s2 = s_src[j+2], s3 = s_src[j+3];
            float e0 = s_ex[hh][j],   e1 = s_ex[hh][j+1];
            float e2 = s_ex[hh][j+2], e3 = s_ex[hh][j+3];
            uint4 h0 = gh[s0 * 32 + t];
            uint4 h1 = gh[s1 * 32 + t];
            uint4 h2 = gh[s2 * 32 + t];
            uint4 h3 = gh[s3 * 32 + t];
            float2 f;
            f = __half22float2(*(const __half2*)&h0.x); acc[0]=fmaf(f.x,e0,acc[0]); acc[1]=fmaf(f.y,e0,acc[1]);
            f = __half22float2(*(const __half2*)&h0.y); acc[2]=fmaf(f.x,e0,acc[2]); acc[3]=fmaf(f.y,e0,acc[3]);
            f = __half22float2(*(const __half2*)&h0.z); acc[4]=fmaf(f.x,e0,acc[4]); acc[5]=fmaf(f.y,e0,acc[5]);
            f = __half22float2(*(const __half2*)&h0.w); acc[6]=fmaf(f.x,e0,acc[6]); acc[7]=fmaf(f.y,e0,acc[7]);
            f = __half22float2(*(const __half2*)&h1.x); acc[0]=fmaf(f.x,e1,acc[0]); acc[1]=fmaf(f.y,e1,acc[1]);
            f = __half22float2(*(const __half2*)&h1.y); acc[2]=fmaf(f.x,e1,acc[2]); acc[3]=fmaf(f.y,e1,acc[3]);
            f = __half22float2(*(const __half2*)&h1.z); acc[4]=fmaf(f.x,e1,acc[4]); acc[5]=fmaf(f.y,e1,acc[5]);
            f = __half22float2(*(const __half2*)&h1.w); acc[6]=fmaf(f.x,e1,acc[6]); acc[7]=fmaf(f.y,e1,acc[7]);
            f = __half22float2(*(const __half2*)&h2.x); acc[0]=fmaf(f.x,e2,acc[0]); acc[1]=fmaf(f.y,e2,acc[1]);
            f = __half22float2(*(const __half2*)&h2.y); acc[2]=fmaf(f.x,e2,acc[2]); acc[3]=fmaf(f.y,e2,acc[3]);
            f = __half22float2(*(const __half2*)&h2.z); acc[4]=fmaf(f.x,e2,acc[4]); acc[5]=fmaf(f.y,e2,acc[5]);
            f = __half22float2(*(const __half2*)&h2.w); acc[6]=fmaf(f.x,e2,acc[6]); acc[7]=fmaf(f.y,e2,acc[7]);
            f = __half22float2(*(const __half2*)&h3.x); acc[0]=fmaf(f.x,e3,acc[0]); acc[1]=fmaf(f.y,e3,acc[1]);
            f = __half22float2(*(const __half2*)&h3.y); acc[2]=fmaf(f.x,e3,acc[2]); acc[3]=fmaf(f.y,e3,acc[3]);
            f = __half22float2(*(const __half2*)&h3.z); acc[4]=fmaf(f.x,e3,acc[4]); acc[5]=fmaf(f.y,e3,acc[5]);
            f = __half22float2(*(const __half2*)&h3.w); acc[6]=fmaf(f.x,e3,acc[6]); acc[7]=fmaf(f.y,e3,acc[7]);
        }
        __syncwarp();
    }
#pragma unroll
    for (int o = 4; o > 0; o >>= 1)
        dpart += __shfl_down_sync(0xffffffffu, dpart, o, 8);
    float den = __shfl_sync(0xffffffffu, dpart, t & 24) + 1e-16f;
    float rden = 1.f / den;

    float c0 = fmaf(acc[0], rden, bg0.x); c0 = (c0 > 0.f) ? c0 : (__expf(c0) - 1.f);
    float c1 = fmaf(acc[1], rden, bg0.y); c1 = (c1 > 0.f) ? c1 : (__expf(c1) - 1.f);
    float c2 = fmaf(acc[2], rden, bg0.z); c2 = (c2 > 0.f) ? c2 : (__expf(c2) - 1.f);
    float c3 = fmaf(acc[3], rden, bg0.w); c3 = (c3 > 0.f) ? c3 : (__expf(c3) - 1.f);
    float c4 = fmaf(acc[4], rden, bg1.x); c4 = (c4 > 0.f) ? c4 : (__expf(c4) - 1.f);
    float c5 = fmaf(acc[5], rden, bg1.y); c5 = (c5 > 0.f) ? c5 : (__expf(c5) - 1.f);
    float c6 = fmaf(acc[6], rden, bg1.z); c6 = (c6 > 0.f) ? c6 : (__expf(c6) - 1.f);
    float c7 = fmaf(acc[7], rden, bg1.w); c7 = (c7 > 0.f) ? c7 : (__expf(c7) - 1.f);
    float agg0 = 0.25f * (c0 + c1 + c2 + c3);
    float agg1 = 0.25f * (c4 + c5 + c6 + c7);

    float yn0 = yv.x + (SP1 * agg0 - 2.f * SP1 * SP1 * yv.x - SP1 * SP1 * xv.x);
    float xn0 = xv.x + yn0;
    float yn1 = yv.y + (SP1 * agg1 - 2.f * SP1 * SP1 * yv.y - SP1 * SP1 * xv.y);
    float xn1 = xv.y + yn1;

    float px = xn0 * xn0 + xn1 * xn1;
    float py = yn0 * yn0 + yn1 * yn1;
#pragma unroll
    for (int o = 16; o > 0; o >>= 1){
        px += __shfl_xor_sync(0xffffffffu, px, o);
        py += __shfl_xor_sync(0xffffffffu, py, o);
    }
    float rx = rsqrtf(px * (1.f / NHID) + 1e-5f);
    float ry = rsqrtf(py * (1.f / NHID) + 1e-5f);
    float xo0 = xn0 * rx, xo1 = xn1 * rx;
    ((float2*)g_X)[n * 32 + t] = make_float2(xo0, xo1);
    if (!FINAL){
        ((float2*)g_Y)[n * 32 + t] = make_float2(yn0 * ry, yn1 * ry);
        ((half2*)g_Xh)[n * 32 + t] = __floats2half2_rn(xo0, xo1);
    }
}

// ---------------- decoder: out = X @ W_dec + b_dec ----------------
__global__ void k_decoder(const float* __restrict__ Wd,
                          const float* __restrict__ bd,
                          float* __restrict__ out){
    int gid = blockIdx.x * blockDim.x + threadIdx.x;
    if (gid >= N_NODES * NCLASS) return;
    int n = gid >> 4, j = gid & 15;
    float acc = bd[j];
#pragma unroll
    for (int k = 0; k < NHID; k++)
        acc = fmaf(g_X[n * NHID + k], Wd[k * NCLASS + j], acc);
    out[gid] = acc;
}

extern "C" void kernel_launch(void* const* d_in, const int* in_sizes, int n_in,
                              void* d_out, int out_size){
    const float* x    = (const float*)d_in[0];
    const int*   ei   = (const int*)d_in[1];
    const float* We   = (const float*)d_in[2];
    const float* be   = (const float*)d_in[3];
    const float* Wg   = (const float*)d_in[4];
    const float* atts = (const float*)d_in[5];
    const float* attd = (const float*)d_in[6];
    const float* bg   = (const float*)d_in[7];
    const float* Wd   = (const float*)d_in[8];
    const float* bd   = (const float*)d_in[9];
    float* out = (float*)d_out;

    // side stream + events (host handles only; created once, no device alloc)
    static cudaStream_t s2 = 0;
    static cudaEvent_t evFork = 0, evJoin = 0;
    if (!s2){
        cudaStreamCreateWithFlags(&s2, cudaStreamNonBlocking);
        cudaEventCreateWithFlags(&evFork, cudaEventDisableTiming);
        cudaEventCreateWithFlags(&evJoin, cudaEventDisableTiming);
    }

    // fork: CSR build runs concurrently with encoder + first projection
    cudaEventRecord(evFork, 0);
    cudaStreamWaitEvent(s2, evFork, 0);
    k_detect <<<1, 32, 0, s2>>>((const unsigned*)ei);
    k_hist   <<<(E_TOT + 255)/256, 256, 0, s2>>>(ei);
    k_scan   <<<1, 1024, 0, s2>>>();
    k_scatter<<<(E_TOT + 255)/256, 256, 0, s2>>>(ei);
    cudaEventRecord(evJoin, s2);

    k_encoder<<<N_NODES/16 + 1, 64>>>(x, We, be, Wg, atts, attd);
    k_gat_proj<<<NPAD/64, 256>>>();
    cudaStreamWaitEvent(0, evJoin, 0);   // join: agg needs the CSR
    k_node_agg_t<false><<<N_NODES, 32>>>(bg);
    k_gat_proj<<<NPAD/64, 256>>>();
    k_node_agg_t<false><<<N_NODES, 32>>>(bg);
    k_gat_proj<<<NPAD/64, 256>>>();
    k_node_agg_t<true> <<<N_NODES, 32>>>(bg);
    k_decoder<<<(N_NODES*NCLASS + 255)/256, 256>>>(Wd, bd, out);
}

// round 16
// speedup vs baseline: 1.0352x; 1.0352x over previous
#include <cuda_runtime.h>
#include <cuda_fp16.h>
#include <math.h>

#define N_NODES 20000
#define NPAD    20032   // padded to multiple of 64 (proj tile)
#define N_EDGES 320000
#define E_TOT   340000  // edges + self loops
#define NFEAT   128
#define NHID    64
#define HEADS   4
#define HH      256     // HEADS*NHID
#define NCLASS  16
#define CAP     96      // bucket capacity per destination (P(deg>96) < 1e-30)

// softplus(1.0)
#define SP1 1.3132616875182228f

// ---------------- scratch (device globals, no allocation) ----------------
__device__ int    g_is64;
__device__ int    g_cnt[N_NODES];   // ZERO invariant: statically zero; re-zeroed off-path each launch
__device__ int    g_csrc[N_NODES*CAP];      // bucketed source lists (row n at n*CAP)
__device__ float  g_watt[NHID*8];           // folded attention weights (4 src, 4 dst cols)
__device__ __align__(16) float  g_X[N_NODES*NHID];
__device__ __align__(16) float  g_Y[N_NODES*NHID];
__device__ __align__(16) __half g_Xh[NPAD*NHID];    // fp16 copy of X (proj input)
__device__ __align__(16) __half g_WgT[HH*NHID];     // fp16 Wg transposed [n][k]
__device__ __align__(16) __half g_h[NPAD*HH];       // fp16 projected features
__device__ __align__(16) float  g_asrc[NPAD*HEADS];
__device__ __align__(16) float  g_adst[NPAD*HEADS];

// decode one edge's (src,dst) from raw edge_index (int32 or int64)
__device__ __forceinline__ void edge_sd(const int* __restrict__ w, int e, int& s, int& d){
    if (e < N_EDGES){
        if (g_is64){ s = w[2*e]; d = w[2*(N_EDGES + e)]; }
        else       { s = w[e];   d = w[N_EDGES + e]; }
    } else {
        s = d = e - N_EDGES;                // self loop
    }
}

// ---------------- dtype detect (1 warp) ----------------
__global__ void k_detect(const unsigned* __restrict__ w){
    if (threadIdx.x == 0){
        // int64 inputs (< 2^31) have all-odd-word zeros in the first 128 words
        int all0 = 1;
        for (int i = 1; i < 128; i += 2) if (w[i] != 0u) all0 = 0;
        g_is64 = all0;
    }
}

// ---------------- bucket scatter: one pass, no scan needed ----------------
__global__ void k_scatter(const int* __restrict__ w){
    int e = blockIdx.x * blockDim.x + threadIdx.x;
    if (e >= E_TOT) return;
    int s, d; edge_sd(w, e, s, d);
    int pos = atomicAdd(&g_cnt[d], 1);
    if (pos < CAP) g_csrc[d * CAP + pos] = s;
}

// ---------------- cleanup: restore zero invariant for next graph replay ----------------
__global__ void k_zero_cnt(){
    int gid = blockIdx.x * blockDim.x + threadIdx.x;
    if (gid < N_NODES) g_cnt[gid] = 0;
}

// ---------------- encoder: Y = relu(x @ W_enc + b_enc); X = Y (fp32 + fp16 copy) ----------------
// extra last block: fold attention weights + transpose Wg to fp16
__global__ void k_encoder(const float* __restrict__ x,
                          const float* __restrict__ We,
                          const float* __restrict__ be,
                          const float* __restrict__ Wg,
                          const float* __restrict__ atts,
                          const float* __restrict__ attd){
    int t = threadIdx.x;
    if (blockIdx.x == N_NODES/16){
        // w_att = Wg @ [atts|attd]; thread t = row k of Wg, 8 outputs
#pragma unroll
        for (int o = 0; o < 8; o++){
            const float* av = (o < 4) ? (atts + (o & 3) * NHID) : (attd + (o & 3) * NHID);
            const float* wr = Wg + t * HH + (o & 3) * NHID;
            float a = 0.f;
#pragma unroll 8
            for (int f = 0; f < NHID; f++) a = fmaf(wr[f], av[f], a);
            g_watt[t * 8 + o] = a;
        }
        // WgT fp16 [n][k]
        for (int i = t; i < HH * NHID; i += 64){
            int n = i >> 6, k = i & 63;
            g_WgT[i] = __float2half_rn(Wg[k * HH + n]);
        }
        return;
    }
    int nb = blockIdx.x * 16;
    __shared__ float4 xs4[16][NFEAT/4];
    for (int r = t; r < 16 * (NFEAT/4); r += 64)
        xs4[r >> 5][r & 31] = ((const float4*)x)[(nb + (r >> 5)) * (NFEAT/4) + (r & 31)];
    __syncthreads();
    float acc[16];
    float b = be[t];
#pragma unroll
    for (int m = 0; m < 16; m++) acc[m] = b;
    for (int k4 = 0; k4 < NFEAT/4; k4++){
        float w0 = We[(4*k4+0) * NHID + t];
        float w1 = We[(4*k4+1) * NHID + t];
        float w2 = We[(4*k4+2) * NHID + t];
        float w3 = We[(4*k4+3) * NHID + t];
#pragma unroll
        for (int m = 0; m < 16; m++){
            float4 xv = xs4[m][k4];
            acc[m] = fmaf(xv.x, w0, acc[m]);
            acc[m] = fmaf(xv.y, w1, acc[m]);
            acc[m] = fmaf(xv.z, w2, acc[m]);
            acc[m] = fmaf(xv.w, w3, acc[m]);
        }
    }
#pragma unroll
    for (int m = 0; m < 16; m++){
        float v = fmaxf(acc[m], 0.f);
        g_Y[(nb + m) * NHID + t] = v;
        g_X[(nb + m) * NHID + t] = v;
        g_Xh[(nb + m) * NHID + t] = __float2half_rn(v);
    }
}

// ---------------- per-layer projection via HMMA: h = X @ W_gat (+ a_src/a_dst) ----------------
// 64 nodes per block, 256 threads = 8 warps
// warp w: m-group = w&3 (rows (w&3)*16..+15), n-half = w>>2 (128 cols), 16 m16n8 tiles
// smem rows padded to 72 halves -> conflict-free fragment loads
__global__ void k_gat_proj(){
    __shared__ __half Xs[64*72];     // 9 KB
    __shared__ __half Ws[256*72];    // 36 KB
    __shared__ float  watt_s[NHID*8];// 2 KB
    int nb = blockIdx.x * 64;
    int t  = threadIdx.x;

#pragma unroll
    for (int i = 0; i < 2; i++){
        int idx = t + i*256;                 // 0..511 uint4s of X tile
        int row = idx >> 3, seg = idx & 7;
        uint4 v = ((const uint4*)g_Xh)[(nb + row)*8 + seg];
        *((uint4*)(Xs + row*72 + seg*8)) = v;
    }
#pragma unroll
    for (int i = 0; i < 8; i++){
        int idx = t + i*256;                 // 0..2047 uint4s of WgT
        int row = idx >> 3, seg = idx & 7;
        uint4 v = ((const uint4*)g_WgT)[idx];
        *((uint4*)(Ws + row*72 + seg*8)) = v;
    }
    for (int r = t; r < NHID*8; r += 256) watt_s[r] = g_watt[r];
    __syncthreads();

    int w = t >> 5, lane = t & 31;
    int gid = lane >> 2, tig = lane & 3;
    int mg = w & 3, nh = w >> 2;

    float acc[16][4];
#pragma unroll
    for (int i = 0; i < 16; i++){
        acc[i][0] = 0.f; acc[i][1] = 0.f; acc[i][2] = 0.f; acc[i][3] = 0.f;
    }
    const unsigned* Xs32 = (const unsigned*)Xs;   // b32 units, row stride 36
    const unsigned* Ws32 = (const unsigned*)Ws;
    int r0 = mg*16 + gid;
#pragma unroll
    for (int ks = 0; ks < 4; ks++){
        unsigned a0 = Xs32[ r0      *36 + ks*8     + tig];
        unsigned a1 = Xs32[(r0 + 8) *36 + ks*8     + tig];
        unsigned a2 = Xs32[ r0      *36 + ks*8 + 4 + tig];
        unsigned a3 = Xs32[(r0 + 8) *36 + ks*8 + 4 + tig];
#pragma unroll
        for (int nt = 0; nt < 16; nt++){
            int n = (nh*16 + nt)*8 + gid;
            unsigned b0 = Ws32[n*36 + ks*8     + tig];
            unsigned b1 = Ws32[n*36 + ks*8 + 4 + tig];
            asm volatile(
                "mma.sync.aligned.m16n8k16.row.col.f32.f16.f16.f32 "
                "{%0,%1,%2,%3}, {%4,%5,%6,%7}, {%8,%9}, {%0,%1,%2,%3};"
                : "+f"(acc[nt][0]), "+f"(acc[nt][1]), "+f"(acc[nt][2]), "+f"(acc[nt][3])
                : "r"(a0), "r"(a1), "r"(a2), "r"(a3), "r"(b0), "r"(b1));
        }
    }
    // epilogue: c0,c1 -> (row gid, cols 2tig,2tig+1); c2,c3 -> row gid+8
#pragma unroll
    for (int nt = 0; nt < 16; nt++){
        int c  = (nh*16 + nt)*8 + tig*2;
        int rr0 = nb + mg*16 + gid;
        ((half2*)g_h)[( rr0      * HH + c) >> 1] = __floats2half2_rn(acc[nt][0], acc[nt][1]);
        ((half2*)g_h)[((rr0 + 8) * HH + c) >> 1] = __floats2half2_rn(acc[nt][2], acc[nt][3]);
    }

    // attention scores from fp16 X: 512 outputs, 2 per thread
#pragma unroll
    for (int i = 0; i < 2; i++){
        int idx = t + i*256;
        int m = idx >> 3, o = idx & 7;
        float a = 0.f;
#pragma unroll 8
        for (int k = 0; k < NHID; k++)
            a = fmaf(__half2float(Xs[m*72 + k]), watt_s[k*8 + o], a);
        if (o < 4) g_asrc[(nb + m) * HEADS + o] = a;
        else       g_adst[(nb + m) * HEADS + (o - 4)] = a;
    }
}

// ---------------- fused per-node: attention + gather + normalize + GraphCON ----------------
// one block = one WARP = one destination node; lane t owns channels 8t..8t+7
// windows padded (clamped src, zero weight) so inner loop is branch-free unroll-4
// softmax without max-subtraction: ratios identical, |e| is small so exp is safe
// FINAL: skip dead g_Y / g_Xh stores in the last layer (g_X still feeds decoder)
template<bool FINAL>
__global__ void k_node_agg_t(const float* __restrict__ bg){
    int n = blockIdx.x;
    int t = threadIdx.x;                 // 0..31
    int hh = t >> 3;                     // head of this lane's channels
    int r0 = n * CAP;
    int deg = g_cnt[n];

    __shared__ int   s_src[32];
    __shared__ float s_ex[HEADS][32];

    // prefetch epilogue operands (hide behind gather)
    float2 xv = ((const float2*)g_X)[n * 32 + t];
    float2 yv = ((const float2*)g_Y)[n * 32 + t];
    float4 bg0 = ((const float4*)bg)[2*t];
    float4 bg1 = ((const float4*)bg)[2*t + 1];
    float4 bdst = ((const float4*)g_adst)[n];

    const uint4* gh = (const uint4*)g_h;   // 8 halves per uint4; row stride HH/8 = 32
    float acc[8];
#pragma unroll
    for (int i = 0; i < 8; i++) acc[i] = 0.f;
    float dpart = 0.f;

    for (int base = 0; base < deg; base += 32){
        int cnt = min(32, deg - base);
        // stage all 32 lanes: clamp index, zero weight beyond cnt
        {
            int idx = base + t;
            int cl  = (idx < deg) ? idx : (deg - 1);
            float mask = (idx < deg) ? 1.f : 0.f;
            int s = g_csrc[r0 + cl];
            s_src[t] = s;
            float4 a = ((const float4*)g_asrc)[s];
            float v;
            v = a.x + bdst.x; v = (v > 0.f) ? v : 0.2f * v; s_ex[0][t] = __expf(v) * mask;
            v = a.y + bdst.y; v = (v > 0.f) ? v : 0.2f * v; s_ex[1][t] = __expf(v) * mask;
            v = a.z + bdst.z; v = (v > 0.f) ? v : 0.2f * v; s_ex[2][t] = __expf(v) * mask;
            v = a.w + bdst.w; v = (v > 0.f) ? v : 0.2f * v; s_ex[3][t] = __expf(v) * mask;
        }
        __syncwarp();
#pragma unroll
        for (int j = 0; j < 4; j++) dpart += s_ex[hh][(t & 7) + 8*j];
        int cntP = (cnt + 3) & ~3;
        for (int j = 0; j < cntP; j += 4){
            int s0 = s_src[j],   s1 = s_src[j+1];
            int s2 = s_src[j+2], s3 = s_src[j+3];
            float e0 = s_ex[hh][j],   e1 = s_ex[hh][j+1];
            float e2 = s_ex[hh][j+2], e3 = s_ex[hh][j+3];
            uint4 h0 = gh[s0 * 32 + t];
            uint4 h1 = gh[s1 * 32 + t];
            uint4 h2 = gh[s2 * 32 + t];
            uint4 h3 = gh[s3 * 32 + t];
            float2 f;
            f = __half22float2(*(const __half2*)&h0.x); acc[0]=fmaf(f.x,e0,acc[0]); acc[1]=fmaf(f.y,e0,acc[1]);
            f = __half22float2(*(const __half2*)&h0.y); acc[2]=fmaf(f.x,e0,acc[2]); acc[3]=fmaf(f.y,e0,acc[3]);
            f = __half22float2(*(const __half2*)&h0.z); acc[4]=fmaf(f.x,e0,acc[4]); acc[5]=fmaf(f.y,e0,acc[5]);
            f = __half22float2(*(const __half2*)&h0.w); acc[6]=fmaf(f.x,e0,acc[6]); acc[7]=fmaf(f.y,e0,acc[7]);
            f = __half22float2(*(const __half2*)&h1.x); acc[0]=fmaf(f.x,e1,acc[0]); acc[1]=fmaf(f.y,e1,acc[1]);
            f = __half22float2(*(const __half2*)&h1.y); acc[2]=fmaf(f.x,e1,acc[2]); acc[3]=fmaf(f.y,e1,acc[3]);
            f = __half22float2(*(const __half2*)&h1.z); acc[4]=fmaf(f.x,e1,acc[4]); acc[5]=fmaf(f.y,e1,acc[5]);
            f = __half22float2(*(const __half2*)&h1.w); acc[6]=fmaf(f.x,e1,acc[6]); acc[7]=fmaf(f.y,e1,acc[7]);
            f = __half22float2(*(const __half2*)&h2.x); acc[0]=fmaf(f.x,e2,acc[0]); acc[1]=fmaf(f.y,e2,acc[1]);
            f = __half22float2(*(const __half2*)&h2.y); acc[2]=fmaf(f.x,e2,acc[2]); acc[3]=fmaf(f.y,e2,acc[3]);
            f = __half22float2(*(const __half2*)&h2.z); acc[4]=fmaf(f.x,e2,acc[4]); acc[5]=fmaf(f.y,e2,acc[5]);
            f = __half22float2(*(const __half2*)&h2.w); acc[6]=fmaf(f.x,e2,acc[6]); acc[7]=fmaf(f.y,e2,acc[7]);
            f = __half22float2(*(const __half2*)&h3.x); acc[0]=fmaf(f.x,e3,acc[0]); acc[1]=fmaf(f.y,e3,acc[1]);
            f = __half22float2(*(const __half2*)&h3.y); acc[2]=fmaf(f.x,e3,acc[2]); acc[3]=fmaf(f.y,e3,acc[3]);
            f = __half22float2(*(const __half2*)&h3.z); acc[4]=fmaf(f.x,e3,acc[4]); acc[5]=fmaf(f.y,e3,acc[5]);
            f = __half22float2(*(const __half2*)&h3.w); acc[6]=fmaf(f.x,e3,acc[6]); acc[7]=fmaf(f.y,e3,acc[7]);
        }
        __syncwarp();
    }
#pragma unroll
    for (int o = 4; o > 0; o >>= 1)
        dpart += __shfl_down_sync(0xffffffffu, dpart, o, 8);
    float den = __shfl_sync(0xffffffffu, dpart, t & 24) + 1e-16f;
    float rden = 1.f / den;

    float c0 = fmaf(acc[0], rden, bg0.x); c0 = (c0 > 0.f) ? c0 : (__expf(c0) - 1.f);
    float c1 = fmaf(acc[1], rden, bg0.y); c1 = (c1 > 0.f) ? c1 : (__expf(c1) - 1.f);
    float c2 = fmaf(acc[2], rden, bg0.z); c2 = (c2 > 0.f) ? c2 : (__expf(c2) - 1.f);
    float c3 = fmaf(acc[3], rden, bg0.w); c3 = (c3 > 0.f) ? c3 : (__expf(c3) - 1.f);
    float c4 = fmaf(acc[4], rden, bg1.x); c4 = (c4 > 0.f) ? c4 : (__expf(c4) - 1.f);
    float c5 = fmaf(acc[5], rden, bg1.y); c5 = (c5 > 0.f) ? c5 : (__expf(c5) - 1.f);
    float c6 = fmaf(acc[6], rden, bg1.z); c6 = (c6 > 0.f) ? c6 : (__expf(c6) - 1.f);
    float c7 = fmaf(acc[7], rden, bg1.w); c7 = (c7 > 0.f) ? c7 : (__expf(c7) - 1.f);
    float agg0 = 0.25f * (c0 + c1 + c2 + c3);
    float agg1 = 0.25f * (c4 + c5 + c6 + c7);

    float yn0 = yv.x + (SP1 * agg0 - 2.f * SP1 * SP1 * yv.x - SP1 * SP1 * xv.x);
    float xn0 = xv.x + yn0;
    float yn1 = yv.y + (SP1 * agg1 - 2.f * SP1 * SP1 * yv.y - SP1 * SP1 * xv.y);
    float xn1 = xv.y + yn1;

    float px = xn0 * xn0 + xn1 * xn1;
    float py = yn0 * yn0 + yn1 * yn1;
#pragma unroll
    for (int o = 16; o > 0; o >>= 1){
        px += __shfl_xor_sync(0xffffffffu, px, o);
        py += __shfl_xor_sync(0xffffffffu, py, o);
    }
    float rx = rsqrtf(px * (1.f / NHID) + 1e-5f);
    float ry = rsqrtf(py * (1.f / NHID) + 1e-5f);
    float xo0 = xn0 * rx, xo1 = xn1 * rx;
    ((float2*)g_X)[n * 32 + t] = make_float2(xo0, xo1);
    if (!FINAL){
        ((float2*)g_Y)[n * 32 + t] = make_float2(yn0 * ry, yn1 * ry);
        ((half2*)g_Xh)[n * 32 + t] = __floats2half2_rn(xo0, xo1);
    }
}

// ---------------- decoder: out = X @ W_dec + b_dec ----------------
__global__ void k_decoder(const float* __restrict__ Wd,
                          const float* __restrict__ bd,
                          float* __restrict__ out){
    int gid = blockIdx.x * blockDim.x + threadIdx.x;
    if (gid >= N_NODES * NCLASS) return;
    int n = gid >> 4, j = gid & 15;
    float acc = bd[j];
#pragma unroll
    for (int k = 0; k < NHID; k++)
        acc = fmaf(g_X[n * NHID + k], Wd[k * NCLASS + j], acc);
    out[gid] = acc;
}

extern "C" void kernel_launch(void* const* d_in, const int* in_sizes, int n_in,
                              void* d_out, int out_size){
    const float* x    = (const float*)d_in[0];
    const int*   ei   = (const int*)d_in[1];
    const float* We   = (const float*)d_in[2];
    const float* be   = (const float*)d_in[3];
    const float* Wg   = (const float*)d_in[4];
    const float* atts = (const float*)d_in[5];
    const float* attd = (const float*)d_in[6];
    const float* bg   = (const float*)d_in[7];
    const float* Wd   = (const float*)d_in[8];
    const float* bd   = (const float*)d_in[9];
    float* out = (float*)d_out;

    // side stream + events (host handles only; created once, no device alloc)
    static cudaStream_t s2 = 0;
    static cudaEvent_t evFork = 0, evJoin = 0, evFork2 = 0, evJoin2 = 0;
    if (!s2){
        cudaStreamCreateWithFlags(&s2, cudaStreamNonBlocking);
        cudaEventCreateWithFlags(&evFork, cudaEventDisableTiming);
        cudaEventCreateWithFlags(&evJoin, cudaEventDisableTiming);
        cudaEventCreateWithFlags(&evFork2, cudaEventDisableTiming);
        cudaEventCreateWithFlags(&evJoin2, cudaEventDisableTiming);
    }

    // fork 1: bucket build runs concurrently with encoder + first projection
    cudaEventRecord(evFork, 0);
    cudaStreamWaitEvent(s2, evFork, 0);
    k_detect <<<1, 32, 0, s2>>>((const unsigned*)ei);
    k_scatter<<<(E_TOT + 255)/256, 256, 0, s2>>>(ei);
    cudaEventRecord(evJoin, s2);

    k_encoder<<<N_NODES/16 + 1, 64>>>(x, We, be, Wg, atts, attd);
    k_gat_proj<<<NPAD/64, 256>>>();
    cudaStreamWaitEvent(0, evJoin, 0);   // join: agg needs the buckets
    k_node_agg_t<false><<<N_NODES, 32>>>(bg);
    k_gat_proj<<<NPAD/64, 256>>>();
    k_node_agg_t<false><<<N_NODES, 32>>>(bg);
    k_gat_proj<<<NPAD/64, 256>>>();
    k_node_agg_t<true> <<<N_NODES, 32>>>(bg);

    // fork 2: restore the g_cnt zero invariant concurrently with the decoder
    cudaEventRecord(evFork2, 0);
    cudaStreamWaitEvent(s2, evFork2, 0);
    k_zero_cnt<<<(N_NODES + 511)/512, 512, 0, s2>>>();
    cudaEventRecord(evJoin2, s2);

    k_decoder<<<(N_NODES*NCLASS + 255)/256, 256>>>(Wd, bd, out);
    cudaStreamWaitEvent(0, evJoin2, 0);  // rejoin side stream before capture ends
}